// round 2
// baseline (speedup 1.0000x reference)
#include <cuda_runtime.h>
#include <cuda_bf16.h>

#define NN 512
#define BATCH 32
#define TT 4
#define SRC_ELEMS ((size_t)BATCH * 2 * NN * NN)   // 16,777,216
#define TGT_ELEMS ((size_t)BATCH * TT * NN)       // 65,536

// Scratch for FFT results: 128 rows x 512 complex = 512 KB. Allocation-free.
__device__ float2 g_Y[BATCH * TT * NN];

// ---------------------------------------------------------------------------
// Kernel 1: 512-point DFT per (b,t) row via smem twiddle table.
// y[k] = sum_n x[n] * exp(-2*pi*i*k*n/N). Table built once per block with
// sincosf (512 calls/block only); inner loop is pure FMA + LDS.
// ---------------------------------------------------------------------------
__global__ __launch_bounds__(NN) void dft512_kernel(const float* __restrict__ x) {
    __shared__ float  xs[NN];
    __shared__ float2 w[NN];

    const int row = blockIdx.x;       // 0..127  (= b*4 + t)
    const int k   = threadIdx.x;      // 0..511

    xs[k] = x[row * NN + k];
    {
        const float ang = -6.283185307179586f * (float)k / (float)NN;
        float s, c;
        sincosf(ang, &s, &c);
        w[k] = make_float2(c, s);
    }
    __syncthreads();

    float re = 0.0f, im = 0.0f;
    int idx = 0;                      // (k*n) mod 512, maintained incrementally
#pragma unroll 8
    for (int n = 0; n < NN; ++n) {
        const float  xv = xs[n];      // broadcast across lanes
        const float2 wv = w[idx];
        re = fmaf(xv, wv.x, re);
        im = fmaf(xv, wv.y, im);
        idx = (idx + k) & (NN - 1);
    }
    g_Y[row * NN + k] = make_float2(re, im);
}

// ---------------------------------------------------------------------------
// Kernel 2: Bx[k,l] = y[k] * conj(y[l]) * y[(l-k) mod N], averaged over T.
// Block = (b, tile of 8 k-rows). 256 threads: 2 k-rows x 128 lanes x 4 l each.
// All y operands from smem (16 KB). float4 stores to Re & Im planes.
// ---------------------------------------------------------------------------
__global__ __launch_bounds__(256) void bispec_kernel(float* __restrict__ out) {
    __shared__ float2 ys[TT][NN];

    const int b    = blockIdx.y;      // 0..31
    const int kblk = blockIdx.x;      // 0..63 (8 k-rows each)

    {
        const float2* Yb = g_Y + (size_t)b * TT * NN;
        float2* ysf = &ys[0][0];
        for (int i = threadIdx.x; i < TT * NN; i += 256)
            ysf[i] = Yb[i];
    }
    __syncthreads();

    const int lane  = threadIdx.x & 127;   // 0..127
    const int ksub  = threadIdx.x >> 7;    // 0..1
    const int lbase = lane * 4;

    float* outb = out + (size_t)b * 2 * NN * NN;

#pragma unroll
    for (int kk = 0; kk < 8; kk += 2) {
        const int k = kblk * 8 + kk + ksub;

        float re[4] = {0.f, 0.f, 0.f, 0.f};
        float im[4] = {0.f, 0.f, 0.f, 0.f};

#pragma unroll
        for (int t = 0; t < TT; ++t) {
            const float2 yk = ys[t][k];
#pragma unroll
            for (int j = 0; j < 4; ++j) {
                const int l = lbase + j;
                const float2 yl = ys[t][l];
                const float2 yc = ys[t][(l - k) & (NN - 1)];
                // a = y[k] * conj(y[l])
                const float ar = fmaf(yk.x, yl.x,  yk.y * yl.y);
                const float ai = fmaf(yk.y, yl.x, -(yk.x * yl.y));
                // Bx = a * y[(l-k) mod N]; accumulate
                re[j] = fmaf(ar, yc.x, re[j]);
                re[j] = fmaf(-ai, yc.y, re[j]);
                im[j] = fmaf(ar, yc.y, im[j]);
                im[j] = fmaf(ai, yc.x, im[j]);
            }
        }

        const float4 vr = make_float4(re[0] * 0.25f, re[1] * 0.25f,
                                      re[2] * 0.25f, re[3] * 0.25f);
        const float4 vi = make_float4(im[0] * 0.25f, im[1] * 0.25f,
                                      im[2] * 0.25f, im[3] * 0.25f);

        *(float4*)(outb + (size_t)k * NN + lbase) = vr;                       // Re plane
        *(float4*)(outb + (size_t)NN * NN + (size_t)k * NN + lbase) = vi;     // Im plane
    }
}

extern "C" void kernel_launch(void* const* d_in, const int* in_sizes, int n_in,
                              void* d_out, int out_size) {
    const float* target = (const float*)d_in[0];
    float* out = (float*)d_out;

    // Stage 1: 128 DFT rows
    dft512_kernel<<<BATCH * TT, NN>>>(target);

    // Stage 2: bispectrum, 32 x 64 blocks
    dim3 grid(NN / 8, BATCH);
    bispec_kernel<<<grid, 256>>>(out);

    // Output tuple is (source, target): copy target passthrough if present.
    if ((size_t)out_size >= SRC_ELEMS + TGT_ELEMS) {
        cudaMemcpyAsync(out + SRC_ELEMS, target, TGT_ELEMS * sizeof(float),
                        cudaMemcpyDeviceToDevice, 0);
    }
}

// round 3
// speedup vs baseline: 2.1169x; 2.1169x over previous
#include <cuda_runtime.h>
#include <cuda_bf16.h>

#define NN 512
#define BATCH 32
#define TT 4
#define NROWS (BATCH * TT)                        // 128
#define SRC_ELEMS ((size_t)BATCH * 2 * NN * NN)   // 16,777,216
#define TGT_ELEMS ((size_t)NROWS * NN)            // 65,536

// FFT results, SoA. 2 x 256 KB. Allocation-free scratch.
__device__ float g_Yr[NROWS][NN];
__device__ float g_Yi[NROWS][NN];

typedef unsigned long long u64;

// ---- packed f32x2 helpers (FFMA2 is PTX-only; ptxas won't auto-fuse) ------
__device__ __forceinline__ u64 pk2(float lo, float hi) {
    u64 r; asm("mov.b64 %0, {%1, %2};" : "=l"(r) : "f"(lo), "f"(hi)); return r;
}
__device__ __forceinline__ void up2(u64 v, float& lo, float& hi) {
    asm("mov.b64 {%0, %1}, %2;" : "=f"(lo), "=f"(hi) : "l"(v));
}
__device__ __forceinline__ u64 f2mul(u64 a, u64 b) {
    u64 d; asm("mul.rn.f32x2 %0, %1, %2;" : "=l"(d) : "l"(a), "l"(b)); return d;
}
__device__ __forceinline__ u64 f2fma(u64 a, u64 b, u64 c) {
    u64 d; asm("fma.rn.f32x2 %0, %1, %2, %3;" : "=l"(d) : "l"(a), "l"(b), "l"(c)); return d;
}

// ---------------------------------------------------------------------------
// Kernel 1: 512-pt DFT of real input, per row (b,t).
// Hermitian symmetry: compute k=0..255 (256 threads), mirror the rest.
// n-symmetry: fold x[n], x[N-n] into s/d; 255 effective MAC iterations.
// Twiddles by register recurrence, exact sincosf resync every 32 steps.
// ---------------------------------------------------------------------------
__global__ __launch_bounds__(256) void dft512_kernel(const float* __restrict__ x) {
    __shared__ float xs[NN];
    __shared__ float s[NN / 2];   // s[1..255]
    __shared__ float d[NN / 2];

    const int row = blockIdx.x;   // 0..127
    const int tid = threadIdx.x;  // 0..255

    for (int i = tid; i < NN; i += 256) xs[i] = x[row * NN + i];
    __syncthreads();
    if (tid >= 1) {
        s[tid] = xs[tid] + xs[NN - tid];
        d[tid] = xs[tid] - xs[NN - tid];
    }
    __syncthreads();

    const float x0 = xs[0], x256 = xs[NN / 2];
    const int k = tid;
    const float W = 6.283185307179586f / (float)NN;   // theta_k = W*k

    float sts, stc;
    sincosf(W * (float)k, &sts, &stc);                // step = e^{+i theta_k}

    float re = x0 + ((k & 1) ? -x256 : x256);
    float im = 0.0f;
    float alt = 0.0f;                                  // sum (-1)^n s[n]

#pragma unroll 1
    for (int c = 0; c < 8; ++c) {
        const int n0 = c * 32;
        const int ph = (k * n0) & (NN - 1);
        float sn, cs;
        sincosf(W * (float)ph, &sn, &cs);              // exact resync
        float curr = cs, curi = sn;                    // (cos, sin)(theta_k * n)
#pragma unroll
        for (int j = 0; j < 32; ++j) {
            const int n = n0 + j;
            if (n >= 1) {                              // skips only n==0 (c==0,j==0)
                const float sv = s[n];                 // broadcast, conflict-free
                const float dv = d[n];
                re = fmaf(sv, curr, re);
                im = fmaf(-dv, curi, im);              // y[k] -= i*d[n]*sin
                alt = (n & 1) ? (alt - sv) : (alt + sv);
            }
            const float nr = fmaf(curr, stc, -(curi * sts));
            curi = fmaf(curr, sts, curi * stc);
            curr = nr;
        }
    }

    float* Yr = g_Yr[row];
    float* Yi = g_Yi[row];
    Yr[k] = re;
    Yi[k] = im;
    if (k == 0) {
        Yr[NN / 2] = x0 + x256 + alt;                  // Nyquist (real)
        Yi[NN / 2] = 0.0f;
    } else {
        Yr[NN - k] = re;                               // conj mirror
        Yi[NN - k] = -im;
    }
}

// ---------------------------------------------------------------------------
// Kernel 2: Bx[k,l] = y[k]*conj(y[l])*y[(l-k) mod N], averaged over T.
// Block: 256 thr = 2 k-groups x 128 lanes. Thread tile: 4 k x 4 l (consec).
// SoA smem, warp-contiguous LDS.128 (conflict-free), 8-value yc window
// reused across the 4x4 tile, all math as packed f32x2 over l-pairs.
// ---------------------------------------------------------------------------
__global__ __launch_bounds__(256, 2) void bispec_kernel(float* __restrict__ out) {
    __shared__ float ysr[TT][NN];
    __shared__ float ysi[TT][NN];

    const int b    = blockIdx.y;    // 0..31
    const int kblk = blockIdx.x;    // 0..63 (8 k each)

    {
        const float4* srcr = (const float4*)g_Yr[b * TT];
        const float4* srci = (const float4*)g_Yi[b * TT];
        float4* dr = (float4*)&ysr[0][0];
        float4* di = (float4*)&ysi[0][0];
        for (int i = threadIdx.x; i < TT * NN / 4; i += 256) {
            dr[i] = srcr[i];
            di[i] = srci[i];
        }
    }
    __syncthreads();

    const int lane  = threadIdx.x & 127;
    const int ksub  = threadIdx.x >> 7;
    const int k0    = kblk * 8 + ksub * 4;
    const int lbase = lane * 4;

    u64 accr[4][2], acci[4][2];
#pragma unroll
    for (int a = 0; a < 4; ++a)
#pragma unroll
        for (int p = 0; p < 2; ++p) { accr[a][p] = 0ull; acci[a][p] = 0ull; }

#pragma unroll
    for (int t = 0; t < TT; ++t) {
        // y[k] broadcast packs (uniform per warp)
        u64 ykr2[4], yki2[4], nykr2[4];
#pragma unroll
        for (int ka = 0; ka < 4; ++ka) {
            const float a = ysr[t][k0 + ka];
            const float c = ysi[t][k0 + ka];
            ykr2[ka]  = pk2(a, a);
            yki2[ka]  = pk2(c, c);
            nykr2[ka] = pk2(-a, -a);
        }
        // y[l]: warp-contiguous float4 (conflict-free)
        const float4 lr = *(const float4*)&ysr[t][lbase];
        const float4 li = *(const float4*)&ysi[t][lbase];
        u64 ylr2[2] = { pk2(lr.x, lr.y), pk2(lr.z, lr.w) };
        u64 yli2[2] = { pk2(li.x, li.y), pk2(li.z, li.w) };

        // yc window: 8 consecutive values [lbase-k0-4 .. lbase-k0+3], aligned
        const int base  = (lbase - k0 - 4 + 1024) & (NN - 1);
        const int base2 = (base + 4) & (NN - 1);
        const float4 c0r = *(const float4*)&ysr[t][base];
        const float4 c1r = *(const float4*)&ysr[t][base2];
        const float4 c0i = *(const float4*)&ysi[t][base];
        const float4 c1i = *(const float4*)&ysi[t][base2];
        const float wr[8] = {c0r.x, c0r.y, c0r.z, c0r.w, c1r.x, c1r.y, c1r.z, c1r.w};
        const float wi[8] = {c0i.x, c0i.y, c0i.z, c0i.w, c1i.x, c1i.y, c1i.z, c1i.w};
        // even- and odd-aligned pair views (hoisted out of the inner loops)
        const u64 cre[4] = { pk2(wr[0],wr[1]), pk2(wr[2],wr[3]), pk2(wr[4],wr[5]), pk2(wr[6],wr[7]) };
        const u64 cie[4] = { pk2(wi[0],wi[1]), pk2(wi[2],wi[3]), pk2(wi[4],wi[5]), pk2(wi[6],wi[7]) };
        const u64 cro[3] = { pk2(wr[1],wr[2]), pk2(wr[3],wr[4]), pk2(wr[5],wr[6]) };
        const u64 cio[3] = { pk2(wi[1],wi[2]), pk2(wi[3],wi[4]), pk2(wi[5],wi[6]) };

#pragma unroll
        for (int ka = 0; ka < 4; ++ka) {
#pragma unroll
            for (int lp = 0; lp < 2; ++lp) {
                const int j0 = 4 + 2 * lp - ka;        // 1..6, compile-time
                const u64 ycr2 = (ka & 1) ? cro[(j0 - 1) >> 1] : cre[j0 >> 1];
                const u64 yci2 = (ka & 1) ? cio[(j0 - 1) >> 1] : cie[j0 >> 1];
                // a = y[k]*conj(y[l])
                const u64 ar2  = f2fma(yki2[ka], yli2[lp], f2mul(ykr2[ka], ylr2[lp]));
                const u64 ai2  = f2fma(nykr2[ka], yli2[lp], f2mul(yki2[ka], ylr2[lp]));
                const u64 nai2 = ai2 ^ 0x8000000080000000ULL;
                // Bx = a * yc
                accr[ka][lp] = f2fma(ar2,  ycr2, accr[ka][lp]);
                accr[ka][lp] = f2fma(nai2, yci2, accr[ka][lp]);
                acci[ka][lp] = f2fma(ar2,  yci2, acci[ka][lp]);
                acci[ka][lp] = f2fma(ai2,  ycr2, acci[ka][lp]);
            }
        }
    }

    float* outb = out + (size_t)b * 2 * NN * NN;
    const u64 quarter = pk2(0.25f, 0.25f);
#pragma unroll
    for (int ka = 0; ka < 4; ++ka) {
        const int k = k0 + ka;
        float r0, r1, r2, r3, i0, i1, i2, i3;
        up2(f2mul(accr[ka][0], quarter), r0, r1);
        up2(f2mul(accr[ka][1], quarter), r2, r3);
        up2(f2mul(acci[ka][0], quarter), i0, i1);
        up2(f2mul(acci[ka][1], quarter), i2, i3);
        *(float4*)&outb[(size_t)k * NN + lbase] = make_float4(r0, r1, r2, r3);
        *(float4*)&outb[(size_t)NN * NN + (size_t)k * NN + lbase] = make_float4(i0, i1, i2, i3);
    }
}

extern "C" void kernel_launch(void* const* d_in, const int* in_sizes, int n_in,
                              void* d_out, int out_size) {
    const float* target = (const float*)d_in[0];
    float* out = (float*)d_out;

    dft512_kernel<<<NROWS, 256>>>(target);

    dim3 grid(NN / 8, BATCH);
    bispec_kernel<<<grid, 256>>>(out);

    if ((size_t)out_size >= SRC_ELEMS + TGT_ELEMS) {
        cudaMemcpyAsync(out + SRC_ELEMS, target, TGT_ELEMS * sizeof(float),
                        cudaMemcpyDeviceToDevice, 0);
    }
}